// round 17
// baseline (speedup 1.0000x reference)
#include <cuda_runtime.h>
#include <cstdint>

// x:     [B=4, N=64,   D=1024] fp32
// cache: [B=4, S=8192, D=1024] fp32
// out:   [B=4, S=8192, D=1024] fp32
// out[b, s, :] = cache[b, s+N, :]   for s <  S-N   (bulk)
// out[b, s, :] = x[b, s-(S-N), :]   for s >= S-N   (tail)
//
// FINAL — roofline-pinned after 16 rounds / 15 configurations. Fused single
// launch, 256 thr/CTA, 64 B/thread via 2x 256-bit ld.global.nc.cs /
// st.global.cs, grid (2048, 4), regs 24, occ ~78%.
// Measured: kernel 35.1-35.9 us (HBM counter ~6.0 TB/s, ~7.6 TB/s
// effective = 94-96% of the 33.6 us spec-HBM floor for the fixed 268.4 MB
// of traffic). Compute pipes <2%, issue ~5% — strictly DRAM-bound; the
// residual gap is R/W turnaround, unreachable from the SM.
// Tested and rejected: VPT 4/8 (reg pressure -> occupancy loss), 512-thr
// CTAs, split kernels (second-launch overhead), persistent grid + SW
// pipelining (occupancy loss), all L2 policies incl. evict_last/.wt
// (path-independent LTS cap; no cross-replay residency for 133 MB cyclic
// read + 134 MB write vs 126 MB L2), cudaMemcpy2DAsync (2.4x slower).
// Indexing in 32-byte (float8) units; all offsets are multiples of 8
// floats, so 256-bit alignment holds everywhere.

static constexpr int B  = 4;
static constexpr int S  = 8192;
static constexpr int D  = 1024;
static constexpr int N  = 64;
static constexpr int D8 = D / 8;                          // 128 float8 per row
static constexpr int ROW8_PER_B  = S * D8;                // 1,048,576
static constexpr int BULK8_PER_B = (S - N) * D8;          // 1,040,384
static constexpr int SHIFT8      = N * D8;                // 8,192
static constexpr int TAIL8_PER_B = N * D8;                // 8,192

static constexpr int THREADS = 256;
static constexpr int VPT     = 2;                         // float8 per thread (64 B)
static constexpr int CHUNK   = THREADS * VPT;             // 512 float8 per CTA
static constexpr int BULK_BLOCKS = BULK8_PER_B / CHUNK;        // 2032
static constexpr int TAIL_BLOCKS = TAIL8_PER_B / CHUNK;        // 16
static constexpr int BLOCKS_X    = BULK_BLOCKS + TAIL_BLOCKS;  // 2048

struct alignas(32) f32x8 { float v[8]; };

__device__ __forceinline__ f32x8 ldg256_nc_cs(const f32x8* p) {
    f32x8 r;
    asm("ld.global.nc.cs.v8.f32 {%0,%1,%2,%3,%4,%5,%6,%7}, [%8];"
        : "=f"(r.v[0]), "=f"(r.v[1]), "=f"(r.v[2]), "=f"(r.v[3]),
          "=f"(r.v[4]), "=f"(r.v[5]), "=f"(r.v[6]), "=f"(r.v[7])
        : "l"(p));
    return r;
}

__device__ __forceinline__ void stg256_cs(f32x8* p, const f32x8& r) {
    asm volatile("st.global.cs.v8.f32 [%0], {%1,%2,%3,%4,%5,%6,%7,%8};"
                 :: "l"(p),
                    "f"(r.v[0]), "f"(r.v[1]), "f"(r.v[2]), "f"(r.v[3]),
                    "f"(r.v[4]), "f"(r.v[5]), "f"(r.v[6]), "f"(r.v[7])
                 : "memory");
}

__global__ __launch_bounds__(THREADS)
void roll_fused_kernel(const f32x8* __restrict__ x8,
                       const f32x8* __restrict__ cache8,
                       f32x8* __restrict__ out8)
{
    const int b   = blockIdx.y;
    const int bx  = blockIdx.x;
    const int tid = threadIdx.x;

    const f32x8* src;
    f32x8*       dst;
    if (bx < BULK_BLOCKS) {
        const int base = bx * CHUNK + tid;
        src = cache8 + (size_t)b * ROW8_PER_B + SHIFT8 + base;
        dst = out8   + (size_t)b * ROW8_PER_B + base;
    } else {
        const int tbase = (bx - BULK_BLOCKS) * CHUNK + tid;
        src = x8   + (size_t)b * TAIL8_PER_B + tbase;
        dst = out8 + (size_t)b * ROW8_PER_B + BULK8_PER_B + tbase;
    }

    f32x8 v0 = ldg256_nc_cs(src + 0 * THREADS);
    f32x8 v1 = ldg256_nc_cs(src + 1 * THREADS);
    stg256_cs(dst + 0 * THREADS, v0);
    stg256_cs(dst + 1 * THREADS, v1);
}

extern "C" void kernel_launch(void* const* d_in, const int* in_sizes, int n_in,
                              void* d_out, int out_size)
{
    const f32x8* x8     = (const f32x8*)d_in[0];
    const f32x8* cache8 = (const f32x8*)d_in[1];
    f32x8* out8 = (f32x8*)d_out;

    dim3 grid(BLOCKS_X, B);   // (2048, 4) = 8192 CTAs
    roll_fused_kernel<<<grid, THREADS>>>(x8, cache8, out8);
}